// round 5
// baseline (speedup 1.0000x reference)
#include <cuda_runtime.h>

#define BB 64
#define PP 24564
#define MM 50
#define CC 21
#define TPB 128
#define PPT 4
#define RPB (TPB * PPT)                    // 512 priors per block
#define GXF ((PP + RPB - 1) / RPB)         // 48 blocks per batch

// ---- scratch (zero-init at load; finalize path restores zeros each run) ----
__device__ unsigned long long g_bp[BB * MM];   // packed (iou_bits<<32)|(~p)
__device__ int      g_bt[BB * PP];             // bm | (pos ? 256 : 0)
__device__ double   g_loc_sum, g_conf_sum;
__device__ int      g_npos;
__device__ unsigned g_done_b[BB];
__device__ unsigned g_done;

// ---------------------------------------------------------------------------
__device__ __forceinline__ float focal_term(const float* __restrict__ row, int lab) {
    float mx = row[0];
    #pragma unroll
    for (int c = 1; c < CC; c++) mx = fmaxf(mx, row[c]);
    float sum = 0.0f;
    #pragma unroll
    for (int c = 0; c < CC; c++) sum += __expf(row[c] - mx);
    float ce = mx + __logf(sum) - row[lab];
    float pt = __expf(-ce);
    float om = fmaxf(1.0f - pt, 0.0f);
    return 0.5f * om * sqrtf(om) * ce;         // ALPHA*(1-pt)^GAMMA*ce, GAMMA=1.5
}

__device__ __forceinline__ float loc_term(float4 d, float4 g, float4 l) {
    float dw = d.z - d.x, dh = d.w - d.y;
    float dcx = d.x + 0.5f * dw, dcy = d.y + 0.5f * dh;
    float gw = g.z - g.x, gh = g.w - g.y;
    float gcx = g.x + 0.5f * gw, gcy = g.y + 0.5f * gh;
    float ex = __fdividef(gcx - dcx, dw + 1e-8f);
    float ey = __fdividef(gcy - dcy, dh + 1e-8f);
    float ew = __logf(__fdividef(gw, dw + 1e-8f) + 1e-8f);
    float eh = __logf(__fdividef(gh, dh + 1e-8f) + 1e-8f);
    float tcx = ex * dw + dcx, tcy = ey * dh + dcy;
    float tw = __expf(ew) * dw, th = __expf(eh) * dh;
    float tx0 = tcx - 0.5f * tw, ty0 = tcy - 0.5f * th;
    float tx1 = tcx + 0.5f * tw, ty1 = tcy + 0.5f * th;
    float pcx = l.x * dw + dcx, pcy = l.y * dh + dcy;
    float pw = __expf(l.z) * dw, ph = __expf(l.w) * dh;
    float px0 = pcx - 0.5f * pw, py0 = pcy - 0.5f * ph;
    float px1 = pcx + 0.5f * pw, py1 = pcy + 0.5f * ph;
    float ix0 = fmaxf(px0, tx0), iy0 = fmaxf(py0, ty0);
    float ix1 = fminf(px1, tx1), iy1 = fminf(py1, ty1);
    float iw = fmaxf(ix1 - ix0, 0.0f), ih = fmaxf(iy1 - iy0, 0.0f);
    float inter = iw * ih;
    float pa = (px1 - px0) * (py1 - py0);
    float ta = (tx1 - tx0) * (ty1 - ty0);
    float uni = pa + ta - inter;
    float i2 = __fdividef(inter, uni + 1e-7f);
    float e0x = fminf(px0, tx0), e0y = fminf(py0, ty0);
    float e1x = fmaxf(px1, tx1), e1y = fmaxf(py1, ty1);
    float ewd = fmaxf(e1x - e0x, 0.0f), ehd = fmaxf(e1y - e0y, 0.0f);
    float encl = ewd * ehd;
    float giou = i2 - __fdividef(encl - uni, encl + 1e-7f);
    return 1.0f - giou;
}

// ---------------------------------------------------------------------------
// Single fused kernel: matching (division-free) + provisional losses +
// per-batch force-match fixup (last block of batch) + global finalize.
__global__ void __launch_bounds__(TPB) k_main(const float4* __restrict__ loc,
                                              const float*  __restrict__ conf,
                                              const float4* __restrict__ dbox,
                                              const float4* __restrict__ gt,
                                              const int*    __restrict__ glab,
                                              float* __restrict__ out)
{
    __shared__ float4 s_conf4[RPB * CC / 4];   // 43008 B, 16B-aligned (cp.async dst!)
    __shared__ float4 s_g[MM];
    __shared__ unsigned long long s_best[MM];
    __shared__ float  s_a[MM];
    __shared__ int    s_lab[MM];
    __shared__ int    s_bp[MM];
    __shared__ float  s_red[8];
    __shared__ int    s_redi[4];
    __shared__ int    s_last;

    const float* s_conf = (const float*)s_conf4;

    int tid = threadIdx.x;
    int b = blockIdx.y;
    int p0 = blockIdx.x * RPB;
    int rows = min(RPB, PP - p0);              // 512 or 500; rows*CC % 4 == 0

    // ---- stage conf early via cp.async (hides under match loop) ----
    {
        const char* gsrc = (const char*)(conf + ((size_t)b * PP + (size_t)p0) * CC);
        unsigned sdst = (unsigned)__cvta_generic_to_shared(s_conf4);
        int n16 = rows * CC / 4;
        for (int i = tid; i < n16; i += TPB) {
            asm volatile("cp.async.ca.shared.global [%0], [%1], 16;\n"
                         :: "r"(sdst + i * 16), "l"(gsrc + (size_t)i * 16));
        }
        asm volatile("cp.async.commit_group;\n");
    }

    if (tid < MM) {
        float4 g = gt[b * MM + tid];
        s_g[tid] = g;
        s_a[tid] = (g.z - g.x) * (g.w - g.y);
        s_best[tid] = 0ull;
        s_lab[tid] = glab[b * MM + tid];
    }
    __syncthreads();

    // ---- load 4 priors per thread ----
    float4 d[PPT];
    float  ar[PPT], bn[PPT], bd[PPT];
    int    bm[PPT];
    unsigned ip[PPT];
    #pragma unroll
    for (int j = 0; j < PPT; j++) {
        int p = p0 + tid + j * TPB;
        int pc = (p < PP) ? p : (PP - 1);      // duplicate of PP-1 can only tie
        d[j] = dbox[pc];
        ar[j] = (d[j].z - d[j].x) * (d[j].w - d[j].y);
        bn[j] = -1.0f; bd[j] = 1.0f; bm[j] = 0;
        ip[j] = 0xFFFFFFFFu - (unsigned)pc;
    }

    // ---- division-free match loop ----
    #pragma unroll 2
    for (int m = 0; m < MM; m++) {
        float4 g = s_g[m];
        float am = s_a[m];
        float cur = __uint_as_float(((const unsigned*)&s_best[m])[1]);
        #pragma unroll
        for (int j = 0; j < PPT; j++) {
            float ix0 = fmaxf(d[j].x, g.x), iy0 = fmaxf(d[j].y, g.y);
            float ix1 = fminf(d[j].z, g.z), iy1 = fminf(d[j].w, g.w);
            float iw  = fmaxf(ix1 - ix0, 0.0f), ih = fmaxf(iy1 - iy0, 0.0f);
            float in  = iw * ih;
            float den = ar[j] + am - in;       // > 0 always
            // argmax over m: in/den > bn/bd  <=>  in*bd > bn*den
            if (in * bd[j] > bn[j] * den) { bn[j] = in; bd[j] = den; bm[j] = m; }
            // per-GT best guard: in/den > cur  ~  in > cur*den (rarely taken)
            if (in > cur * den) {
                float iou = __fdividef(in, den);
                atomicMax(&s_best[m],
                          ((unsigned long long)__float_as_uint(iou) << 32) | ip[j]);
            }
        }
    }

    __syncthreads();
    if (tid < MM) atomicMax(&g_bp[b * MM + tid], s_best[tid]);

    asm volatile("cp.async.wait_group 0;\n" ::: "memory");
    __syncthreads();

    // ---- provisional focal + GIoU for this thread's 4 priors ----
    float fl = 0.0f, ll = 0.0f;
    int pos = 0;
    #pragma unroll
    for (int j = 0; j < PPT; j++) {
        int r = tid + j * TPB;
        int p = p0 + r;
        if (p < PP) {
            bool posj = (bn[j] + bn[j] >= bd[j]);      // iou >= 0.5 (exact)
            int lab = posj ? s_lab[bm[j]] : 0;
            fl += focal_term(&s_conf[r * CC], lab);    // stride 21: conflict-free
            g_bt[b * PP + p] = bm[j] | (posj ? 256 : 0);
            if (lab > 0) {
                pos++;
                ll += loc_term(d[j], s_g[bm[j]], loc[(size_t)b * PP + p]);
            }
        }
    }

    // ---- block reduction (4 warps) ----
    #pragma unroll
    for (int o = 16; o; o >>= 1) {
        fl  += __shfl_down_sync(0xFFFFFFFFu, fl, o);
        ll  += __shfl_down_sync(0xFFFFFFFFu, ll, o);
        pos += __shfl_down_sync(0xFFFFFFFFu, pos, o);
    }
    int wid = tid >> 5, lid = tid & 31;
    if (lid == 0) { s_red[wid] = fl; s_red[4 + wid] = ll; s_redi[wid] = pos; }
    __syncthreads();
    if (tid == 0) {
        float f  = s_red[0] + s_red[1] + s_red[2] + s_red[3];
        float l2 = s_red[4] + s_red[5] + s_red[6] + s_red[7];
        int   pc = s_redi[0] + s_redi[1] + s_redi[2] + s_redi[3];
        atomicAdd(&g_conf_sum, (double)f);
        atomicAdd(&g_loc_sum, (double)l2);
        atomicAdd(&g_npos, pc);
    }

    // ---- per-batch completion: last block of batch b does the fixup ----
    __threadfence();                           // publish g_bt stores (all threads)
    __syncthreads();
    if (tid == 0) {
        unsigned t = atomicAdd(&g_done_b[b], 1u);
        s_last = (t == (unsigned)(GXF - 1)) ? 1 : 0;
    }
    __syncthreads();
    if (!s_last) return;

    __threadfence();                           // acquire g_bt / g_bp of other blocks
    if (tid < MM) {
        unsigned long long pk = g_bp[b * MM + tid];
        g_bp[b * MM + tid] = 0ull;             // reset for next run
        s_bp[tid] = (int)(0xFFFFFFFFu - (unsigned)(pk & 0xFFFFFFFFull));
    }
    __syncthreads();

    float dc = 0.0f, dl = 0.0f;
    int dp = 0;
    if (tid < MM) {
        int p = s_bp[tid];
        bool win = (p >= 0 && p < PP);
        for (int m2 = tid + 1; m2 < MM; m2++)  // duplicate p: largest m wins
            if (s_bp[m2] == p) win = false;
        if (win) {
            int v = g_bt[b * PP + p];
            int lab0 = (v & 256) ? s_lab[v & 255] : 0;
            const float* row = conf + ((size_t)b * PP + p) * CC;
            float fl0 = focal_term(row, lab0);         // cancels provisional
            float fl1 = focal_term(row, s_lab[tid]);   // forced label
            dc = fl1 - fl0;
            float4 dd = dbox[p];
            float4 l  = loc[(size_t)b * PP + p];
            float ll1 = loc_term(dd, s_g[tid], l);
            float ll0 = (lab0 > 0) ? loc_term(dd, s_g[v & 255], l) : 0.0f;
            dl = ll1 - ll0;
            dp = 1 - ((lab0 > 0) ? 1 : 0);
        }
    }
    // reduce fixup deltas over first 2 warps
    #pragma unroll
    for (int o = 16; o; o >>= 1) {
        dc += __shfl_down_sync(0xFFFFFFFFu, dc, o);
        dl += __shfl_down_sync(0xFFFFFFFFu, dl, o);
        dp += __shfl_down_sync(0xFFFFFFFFu, dp, o);
    }
    if (lid == 0) { s_red[wid] = dc; s_red[4 + wid] = dl; s_redi[wid] = dp; }
    __syncthreads();
    if (tid == 0) {
        float f = s_red[0] + s_red[1];
        float l = s_red[4] + s_red[5];
        int  pc = s_redi[0] + s_redi[1];
        if (f != 0.0f) atomicAdd(&g_conf_sum, (double)f);
        if (l != 0.0f) atomicAdd(&g_loc_sum, (double)l);
        if (pc != 0)   atomicAdd(&g_npos, pc);
        g_done_b[b] = 0u;                      // reset for next run
        __threadfence();
        unsigned t = atomicAdd(&g_done, 1u);
        if (t == (unsigned)(BB - 1)) {         // globally last fixup: finalize
            __threadfence();
            double ls = atomicAdd(&g_loc_sum, 0.0);
            double cs = atomicAdd(&g_conf_sum, 0.0);
            int np = atomicAdd(&g_npos, 0);
            double denom = (double)(np > 0 ? np : 1);
            float res = (float)(ls / denom) + (float)(cs / denom);
            out[0] = (np == 0) ? 0.0f : res;
            g_loc_sum = 0.0; g_conf_sum = 0.0; g_npos = 0; g_done = 0u;
        }
    }
}

// ---------------------------------------------------------------------------
extern "C" void kernel_launch(void* const* d_in, const int* in_sizes, int n_in,
                              void* d_out, int out_size) {
    const float4* loc  = (const float4*)d_in[0];  // [B,P,4]  f32
    const float*  conf = (const float*)d_in[1];   // [B,P,21] f32
    const float4* dbox = (const float4*)d_in[2];  // [P,4]    f32
    const float4* gt   = (const float4*)d_in[3];  // [B,50,4] f32
    const int*    glab = (const int*)d_in[4];     // [B,50]   i32
    float* out = (float*)d_out;

    dim3 gm(GXF, BB);
    k_main<<<gm, TPB>>>(loc, conf, dbox, gt, glab, out);
}

// round 7
// speedup vs baseline: 1.2993x; 1.2993x over previous
#include <cuda_runtime.h>

#define BB 64
#define PP 24564
#define MM 50
#define CC 21
#define TPB 256
#define PPT 2
#define RPB (TPB * PPT)                    // 512 priors per block
#define GXF ((PP + RPB - 1) / RPB)         // 48 blocks per batch

// ---- scratch (zero-init at load; finalize path restores zeros each run) ----
__device__ unsigned long long g_bp[BB * MM];   // packed (iou_bits<<32)|(~p)
__device__ int      g_bt[BB * PP];             // bm | (pos ? 256 : 0)
__device__ double   g_loc_sum, g_conf_sum;
__device__ int      g_npos;
__device__ unsigned g_done_b[BB];
__device__ unsigned g_done;

// ---------------------------------------------------------------------------
__device__ __forceinline__ float focal_term(const float* __restrict__ row, int lab) {
    float mx = row[0];
    #pragma unroll
    for (int c = 1; c < CC; c++) mx = fmaxf(mx, row[c]);
    float sum = 0.0f;
    #pragma unroll
    for (int c = 0; c < CC; c++) sum += __expf(row[c] - mx);
    float ce = mx + __logf(sum) - row[lab];
    float pt = __expf(-ce);
    float om = fmaxf(1.0f - pt, 0.0f);
    return 0.5f * om * sqrtf(om) * ce;         // ALPHA*(1-pt)^GAMMA*ce, GAMMA=1.5
}

__device__ __forceinline__ float loc_term(float4 d, float4 g, float4 l) {
    float dw = d.z - d.x, dh = d.w - d.y;
    float dcx = d.x + 0.5f * dw, dcy = d.y + 0.5f * dh;
    float gw = g.z - g.x, gh = g.w - g.y;
    float gcx = g.x + 0.5f * gw, gcy = g.y + 0.5f * gh;
    float ex = __fdividef(gcx - dcx, dw + 1e-8f);
    float ey = __fdividef(gcy - dcy, dh + 1e-8f);
    float ew = __logf(__fdividef(gw, dw + 1e-8f) + 1e-8f);
    float eh = __logf(__fdividef(gh, dh + 1e-8f) + 1e-8f);
    float tcx = ex * dw + dcx, tcy = ey * dh + dcy;
    float tw = __expf(ew) * dw, th = __expf(eh) * dh;
    float tx0 = tcx - 0.5f * tw, ty0 = tcy - 0.5f * th;
    float tx1 = tcx + 0.5f * tw, ty1 = tcy + 0.5f * th;
    float pcx = l.x * dw + dcx, pcy = l.y * dh + dcy;
    float pw = __expf(l.z) * dw, ph = __expf(l.w) * dh;
    float px0 = pcx - 0.5f * pw, py0 = pcy - 0.5f * ph;
    float px1 = pcx + 0.5f * pw, py1 = pcy + 0.5f * ph;
    float ix0 = fmaxf(px0, tx0), iy0 = fmaxf(py0, ty0);
    float ix1 = fminf(px1, tx1), iy1 = fminf(py1, ty1);
    float iw = fmaxf(ix1 - ix0, 0.0f), ih = fmaxf(iy1 - iy0, 0.0f);
    float inter = iw * ih;
    float pa = (px1 - px0) * (py1 - py0);
    float ta = (tx1 - tx0) * (ty1 - ty0);
    float uni = pa + ta - inter;
    float i2 = __fdividef(inter, uni + 1e-7f);
    float e0x = fminf(px0, tx0), e0y = fminf(py0, ty0);
    float e1x = fmaxf(px1, tx1), e1y = fmaxf(py1, ty1);
    float ewd = fmaxf(e1x - e0x, 0.0f), ehd = fmaxf(e1y - e0y, 0.0f);
    float encl = ewd * ehd;
    float giou = i2 - __fdividef(encl - uni, encl + 1e-7f);
    return 1.0f - giou;
}

// ---------------------------------------------------------------------------
// Single fused kernel: matching + provisional losses + per-batch force-match
// fixup (last-arriving block of each batch) + global finalize.
__global__ void __launch_bounds__(TPB) k_main(const float4* __restrict__ loc,
                                              const float*  __restrict__ conf,
                                              const float4* __restrict__ dbox,
                                              const float4* __restrict__ gt,
                                              const int*    __restrict__ glab,
                                              float* __restrict__ out)
{
    __shared__ float4 s_conf4[RPB * CC / 4];   // 43008 B, 16B-aligned cp.async dst
    __shared__ float4 s_g[MM];
    __shared__ unsigned long long s_best[MM];
    __shared__ float  s_a[MM];
    __shared__ int    s_lab[MM];
    __shared__ int    s_bp[MM];
    __shared__ float  s_red[16];
    __shared__ int    s_redi[8];
    __shared__ int    s_last;

    const float* s_conf = (const float*)s_conf4;

    int tid = threadIdx.x;
    int b = blockIdx.y;
    int p0 = blockIdx.x * RPB;
    int rows = min(RPB, PP - p0);              // 512 or 500; rows*CC % 4 == 0

    // ---- stage conf early via cp.async (hides under match loop) ----
    {
        const char* gsrc = (const char*)(conf + ((size_t)b * PP + (size_t)p0) * CC);
        unsigned sdst = (unsigned)__cvta_generic_to_shared(s_conf4);
        int n16 = rows * CC / 4;
        for (int i = tid; i < n16; i += TPB) {
            asm volatile("cp.async.ca.shared.global [%0], [%1], 16;\n"
                         :: "r"(sdst + i * 16), "l"(gsrc + (size_t)i * 16));
        }
        asm volatile("cp.async.commit_group;\n");
    }

    if (tid < MM) {
        float4 g = gt[b * MM + tid];
        s_g[tid] = g;
        s_a[tid] = (g.z - g.x) * (g.w - g.y);
        s_best[tid] = 0ull;
        s_lab[tid] = glab[b * MM + tid];
    }
    __syncthreads();

    // ---- match loop: 2 priors per thread, __fdividef IoU ----
    int p1 = p0 + tid;
    int p2 = p1 + TPB;
    bool v2 = (p2 < PP);
    int p2c = v2 ? p2 : (PP - 1);              // duplicate can only tie; tie loses
    float4 d1 = dbox[p1];
    float4 d2 = dbox[p2c];
    float a1 = (d1.z - d1.x) * (d1.w - d1.y);
    float a2 = (d2.z - d2.x) * (d2.w - d2.y);
    float best1 = -1.0f, best2 = -1.0f;
    int bm1 = 0, bm2 = 0;
    unsigned ip1 = 0xFFFFFFFFu - (unsigned)p1;
    unsigned ip2 = 0xFFFFFFFFu - (unsigned)p2c;

    #pragma unroll 10
    for (int m = 0; m < MM; m++) {
        float4 g = s_g[m];
        float am = s_a[m];
        float cur = __uint_as_float(((const unsigned*)&s_best[m])[1]);
        // prior 1
        float ix0 = fmaxf(d1.x, g.x), iy0 = fmaxf(d1.y, g.y);
        float ix1 = fminf(d1.z, g.z), iy1 = fminf(d1.w, g.w);
        float iw  = fmaxf(ix1 - ix0, 0.0f), ih = fmaxf(iy1 - iy0, 0.0f);
        float in1 = iw * ih;
        float iou1 = __fdividef(in1, a1 + am - in1);
        if (iou1 > best1) { best1 = iou1; bm1 = m; }   // strict > = first-max
        // prior 2
        float jx0 = fmaxf(d2.x, g.x), jy0 = fmaxf(d2.y, g.y);
        float jx1 = fminf(d2.z, g.z), jy1 = fminf(d2.w, g.w);
        float jw  = fmaxf(jx1 - jx0, 0.0f), jh = fmaxf(jy1 - jy0, 0.0f);
        float in2 = jw * jh;
        float iou2 = __fdividef(in2, a2 + am - in2);
        if (iou2 > best2) { best2 = iou2; bm2 = m; }
        // per-GT best guard (stale reads only under-admit; atomic decides)
        if (iou1 > cur)
            atomicMax(&s_best[m],
                      ((unsigned long long)__float_as_uint(iou1) << 32) | ip1);
        if (iou2 > cur)
            atomicMax(&s_best[m],
                      ((unsigned long long)__float_as_uint(iou2) << 32) | ip2);
    }

    __syncthreads();
    if (tid < MM) atomicMax(&g_bp[b * MM + tid], s_best[tid]);

    asm volatile("cp.async.wait_group 0;\n" ::: "memory");
    __syncthreads();

    // ---- provisional focal + GIoU for this thread's 2 priors ----
    float fl = 0.0f, ll = 0.0f;
    int pos = 0;
    {
        bool posj = (best1 >= 0.5f);
        int lab = posj ? s_lab[bm1] : 0;
        fl += focal_term(&s_conf[tid * CC], lab);      // stride 21: conflict-free
        g_bt[b * PP + p1] = bm1 | (posj ? 256 : 0);
        if (lab > 0) {
            pos++;
            ll += loc_term(d1, s_g[bm1], loc[(size_t)b * PP + p1]);
        }
    }
    if (v2) {
        bool posj = (best2 >= 0.5f);
        int lab = posj ? s_lab[bm2] : 0;
        fl += focal_term(&s_conf[(tid + TPB) * CC], lab);
        g_bt[b * PP + p2] = bm2 | (posj ? 256 : 0);
        if (lab > 0) {
            pos++;
            ll += loc_term(d2, s_g[bm2], loc[(size_t)b * PP + p2]);
        }
    }

    // ---- block reduction (8 warps) ----
    #pragma unroll
    for (int o = 16; o; o >>= 1) {
        fl  += __shfl_down_sync(0xFFFFFFFFu, fl, o);
        ll  += __shfl_down_sync(0xFFFFFFFFu, ll, o);
        pos += __shfl_down_sync(0xFFFFFFFFu, pos, o);
    }
    int wid = tid >> 5, lid = tid & 31;
    if (lid == 0) { s_red[wid] = fl; s_red[8 + wid] = ll; s_redi[wid] = pos; }
    __syncthreads();
    if (wid == 0) {
        float f  = (lid < 8) ? s_red[lid]     : 0.0f;
        float l2 = (lid < 8) ? s_red[8 + lid] : 0.0f;
        int   pc = (lid < 8) ? s_redi[lid]    : 0;
        #pragma unroll
        for (int o = 4; o; o >>= 1) {
            f  += __shfl_down_sync(0xFFFFFFFFu, f, o);
            l2 += __shfl_down_sync(0xFFFFFFFFu, l2, o);
            pc += __shfl_down_sync(0xFFFFFFFFu, pc, o);
        }
        if (lid == 0) {
            atomicAdd(&g_conf_sum, (double)f);
            atomicAdd(&g_loc_sum, (double)l2);
            atomicAdd(&g_npos, pc);
        }
    }

    // ---- per-batch completion: last block of batch b does the fixup ----
    __threadfence();                           // publish g_bt stores (all threads)
    __syncthreads();
    if (tid == 0) {
        unsigned t = atomicAdd(&g_done_b[b], 1u);
        s_last = (t == (unsigned)(GXF - 1)) ? 1 : 0;
    }
    __syncthreads();
    if (!s_last) return;

    __threadfence();                           // acquire g_bt / g_bp of other blocks
    if (tid < MM) {
        unsigned long long pk = g_bp[b * MM + tid];
        g_bp[b * MM + tid] = 0ull;             // reset for next run
        s_bp[tid] = (int)(0xFFFFFFFFu - (unsigned)(pk & 0xFFFFFFFFull));
    }
    __syncthreads();

    float dc = 0.0f, dl = 0.0f;
    int dp = 0;
    if (tid < MM) {
        int p = s_bp[tid];
        bool win = (p >= 0 && p < PP);
        for (int m2 = tid + 1; m2 < MM; m2++)  // duplicate p: largest m wins
            if (s_bp[m2] == p) win = false;
        if (win) {
            int v = g_bt[b * PP + p];
            int lab0 = (v & 256) ? s_lab[v & 255] : 0;
            const float* row = conf + ((size_t)b * PP + p) * CC;
            float fl0 = focal_term(row, lab0);         // cancels provisional
            float fl1 = focal_term(row, s_lab[tid]);   // forced label
            dc = fl1 - fl0;
            float4 dd = dbox[p];
            float4 l  = loc[(size_t)b * PP + p];
            float ll1 = loc_term(dd, s_g[tid], l);
            float ll0 = (lab0 > 0) ? loc_term(dd, s_g[v & 255], l) : 0.0f;
            dl = ll1 - ll0;
            dp = 1 - ((lab0 > 0) ? 1 : 0);
        }
    }
    // reduce fixup deltas over first 2 warps
    #pragma unroll
    for (int o = 16; o; o >>= 1) {
        dc += __shfl_down_sync(0xFFFFFFFFu, dc, o);
        dl += __shfl_down_sync(0xFFFFFFFFu, dl, o);
        dp += __shfl_down_sync(0xFFFFFFFFu, dp, o);
    }
    if (lid == 0) { s_red[wid] = dc; s_red[8 + wid] = dl; s_redi[wid] = dp; }
    __syncthreads();
    if (tid == 0) {
        float f = s_red[0] + s_red[1];
        float l = s_red[8] + s_red[9];
        int  pc = s_redi[0] + s_redi[1];
        if (f != 0.0f) atomicAdd(&g_conf_sum, (double)f);
        if (l != 0.0f) atomicAdd(&g_loc_sum, (double)l);
        if (pc != 0)   atomicAdd(&g_npos, pc);
        g_done_b[b] = 0u;                      // reset for next run
        __threadfence();
        unsigned t = atomicAdd(&g_done, 1u);
        if (t == (unsigned)(BB - 1)) {         // globally last fixup: finalize
            __threadfence();
            double ls = atomicAdd(&g_loc_sum, 0.0);
            double cs = atomicAdd(&g_conf_sum, 0.0);
            int np = atomicAdd(&g_npos, 0);
            double denom = (double)(np > 0 ? np : 1);
            float res = (float)(ls / denom) + (float)(cs / denom);
            out[0] = (np == 0) ? 0.0f : res;
            g_loc_sum = 0.0; g_conf_sum = 0.0; g_npos = 0; g_done = 0u;
        }
    }
}

// ---------------------------------------------------------------------------
extern "C" void kernel_launch(void* const* d_in, const int* in_sizes, int n_in,
                              void* d_out, int out_size) {
    const float4* loc  = (const float4*)d_in[0];  // [B,P,4]  f32
    const float*  conf = (const float*)d_in[1];   // [B,P,21] f32
    const float4* dbox = (const float4*)d_in[2];  // [P,4]    f32
    const float4* gt   = (const float4*)d_in[3];  // [B,50,4] f32
    const int*    glab = (const int*)d_in[4];     // [B,50]   i32
    float* out = (float*)d_out;

    dim3 gm(GXF, BB);
    k_main<<<gm, TPB>>>(loc, conf, dbox, gt, glab, out);
}

// round 11
// speedup vs baseline: 1.3167x; 1.0134x over previous
#include <cuda_runtime.h>

#define BB 64
#define PP 24564
#define MM 50
#define CC 21
#define NC 64                              // 8x8 spatial cells
#define TPB 256
#define RPB 512
#define GXL ((PP + RPB - 1) / RPB)         // 48 loss blocks per batch

// ---- scratch (zero-init at load; finalize path restores zeros each run) ----
__device__ int      g_perm[PP];
__device__ int      g_pcell[PP];               // (cell<<16) | pos-in-cell
__device__ int      g_ccount[NC];
__device__ int      g_cstart[NC + 1];
__device__ unsigned g_cbb[NC * 4];             // minx,miny,maxx,maxy (float bits)
__device__ unsigned long long g_bp[BB * MM];   // packed (iou_bits<<32)|(~p)
__device__ int      g_bt[BB * PP];             // bm | (pos ? 256 : 0)
__device__ double   g_loc_sum, g_conf_sum;
__device__ int      g_npos;
__device__ unsigned g_done_b[BB];
__device__ unsigned g_done;

// ---------------------------------------------------------------------------
__device__ __forceinline__ float focal_term(const float* __restrict__ row, int lab) {
    float mx = row[0];
    #pragma unroll
    for (int c = 1; c < CC; c++) mx = fmaxf(mx, row[c]);
    float sum = 0.0f;
    #pragma unroll
    for (int c = 0; c < CC; c++) sum += __expf(row[c] - mx);
    float ce = mx + __logf(sum) - row[lab];
    float pt = __expf(-ce);
    float om = fmaxf(1.0f - pt, 0.0f);
    return 0.5f * om * sqrtf(om) * ce;         // ALPHA*(1-pt)^GAMMA*ce, GAMMA=1.5
}

__device__ __forceinline__ float loc_term(float4 d, float4 g, float4 l) {
    float dw = d.z - d.x, dh = d.w - d.y;
    float dcx = d.x + 0.5f * dw, dcy = d.y + 0.5f * dh;
    float gw = g.z - g.x, gh = g.w - g.y;
    float gcx = g.x + 0.5f * gw, gcy = g.y + 0.5f * gh;
    float ex = __fdividef(gcx - dcx, dw + 1e-8f);
    float ey = __fdividef(gcy - dcy, dh + 1e-8f);
    float ew = __logf(__fdividef(gw, dw + 1e-8f) + 1e-8f);
    float eh = __logf(__fdividef(gh, dh + 1e-8f) + 1e-8f);
    float tcx = ex * dw + dcx, tcy = ey * dh + dcy;
    float tw = __expf(ew) * dw, th = __expf(eh) * dh;
    float tx0 = tcx - 0.5f * tw, ty0 = tcy - 0.5f * th;
    float tx1 = tcx + 0.5f * tw, ty1 = tcy + 0.5f * th;
    float pcx = l.x * dw + dcx, pcy = l.y * dh + dcy;
    float pw = __expf(l.z) * dw, ph = __expf(l.w) * dh;
    float px0 = pcx - 0.5f * pw, py0 = pcy - 0.5f * ph;
    float px1 = pcx + 0.5f * pw, py1 = pcy + 0.5f * ph;
    float ix0 = fmaxf(px0, tx0), iy0 = fmaxf(py0, ty0);
    float ix1 = fminf(px1, tx1), iy1 = fminf(py1, ty1);
    float iw = fmaxf(ix1 - ix0, 0.0f), ih = fmaxf(iy1 - iy0, 0.0f);
    float inter = iw * ih;
    float pa = (px1 - px0) * (py1 - py0);
    float ta = (tx1 - tx0) * (ty1 - ty0);
    float uni = pa + ta - inter;
    float i2 = __fdividef(inter, uni + 1e-7f);
    float e0x = fminf(px0, tx0), e0y = fminf(py0, ty0);
    float e1x = fmaxf(px1, tx1), e1y = fmaxf(py1, ty1);
    float ewd = fmaxf(e1x - e0x, 0.0f), ehd = fmaxf(e1y - e0y, 0.0f);
    float encl = ewd * ehd;
    float giou = i2 - __fdividef(encl - uni, encl + 1e-7f);
    return 1.0f - giou;
}

// ---------------------------------------------------------------------------
__global__ void k_prep0() {
    int t = threadIdx.x;
    if (t < NC) {
        g_ccount[t] = 0;
        g_cbb[t * 4 + 0] = 0x7F800000u;   // +inf
        g_cbb[t * 4 + 1] = 0x7F800000u;
        g_cbb[t * 4 + 2] = 0u;
        g_cbb[t * 4 + 3] = 0u;
    }
}

__global__ void k_bucket(const float4* __restrict__ dbox) {
    int p = blockIdx.x * 256 + threadIdx.x;
    if (p >= PP) return;
    float4 d = dbox[p];
    float cx = 0.5f * (d.x + d.z), cy = 0.5f * (d.y + d.w);
    int ix = min(7, max(0, (int)(cx * 8.0f)));
    int iy = min(7, max(0, (int)(cy * 8.0f)));
    int c = iy * 8 + ix;
    int pos = atomicAdd(&g_ccount[c], 1);
    g_pcell[p] = (c << 16) | pos;
    atomicMin(&g_cbb[c * 4 + 0], __float_as_uint(d.x));   // coords >= 0
    atomicMin(&g_cbb[c * 4 + 1], __float_as_uint(d.y));
    atomicMax(&g_cbb[c * 4 + 2], __float_as_uint(d.z));
    atomicMax(&g_cbb[c * 4 + 3], __float_as_uint(d.w));
}

__global__ void k_prep2() {
    if (threadIdx.x == 0) {
        int s = 0;
        for (int c = 0; c < NC; c++) { g_cstart[c] = s; s += g_ccount[c]; }
        g_cstart[NC] = s;
    }
}

__global__ void k_scatter() {
    int p = blockIdx.x * 256 + threadIdx.x;
    if (p >= PP) return;
    int v = g_pcell[p];
    g_perm[g_cstart[v >> 16] + (v & 0xFFFF)] = p;
}

// ---------------------------------------------------------------------------
// Matching with GT-vs-cell-bbox culling. One block per (cell, batch).
__global__ void __launch_bounds__(TPB) k_match(const float4* __restrict__ dbox,
                                               const float4* __restrict__ gt)
{
    __shared__ float4 s_g[MM];
    __shared__ float  s_a[MM];
    __shared__ unsigned long long s_best[MM];
    __shared__ int    s_ml[MM];
    __shared__ int    s_n;

    int tid = threadIdx.x;
    int c = blockIdx.x;
    int b = blockIdx.y;
    int cs = g_cstart[c], ce = g_cstart[c + 1];

    if (tid < MM) {
        float4 g = gt[b * MM + tid];
        s_g[tid] = g;
        s_a[tid] = (g.z - g.x) * (g.w - g.y);
        s_best[tid] = 0ull;
    }
    __syncthreads();

    if (tid == 0) {
        float bx0 = __uint_as_float(g_cbb[c * 4 + 0]);
        float by0 = __uint_as_float(g_cbb[c * 4 + 1]);
        float bx1 = __uint_as_float(g_cbb[c * 4 + 2]);
        float by1 = __uint_as_float(g_cbb[c * 4 + 3]);
        int n = 0;
        for (int m = 0; m < MM; m++) {       // increasing m keeps first-max order
            float4 g = s_g[m];
            if (g.x < bx1 && bx0 < g.z && g.y < by1 && by0 < g.w)
                s_ml[n++] = m;               // strict <: touching => inter=0, skip
        }
        s_n = n;
    }
    __syncthreads();
    int n = s_n;

    for (int i = cs + tid; i < ce; i += TPB) {
        int p = g_perm[i];
        float4 d = dbox[p];
        float a1 = (d.z - d.x) * (d.w - d.y);
        float best = 0.0f;                   // culled pairs are exactly 0; all-zero row -> argmax 0
        int bm = 0;
        unsigned ip = 0xFFFFFFFFu - (unsigned)p;
        for (int k = 0; k < n; k++) {
            int m = s_ml[k];
            float4 g = s_g[m];
            float am = s_a[m];
            float ix0 = fmaxf(d.x, g.x), iy0 = fmaxf(d.y, g.y);
            float ix1 = fminf(d.z, g.z), iy1 = fminf(d.w, g.w);
            float iw  = fmaxf(ix1 - ix0, 0.0f), ih = fmaxf(iy1 - iy0, 0.0f);
            float in  = iw * ih;
            float iou = __fdividef(in, a1 + am - in);
            if (iou > best) { best = iou; bm = m; }    // strict > = first-max
            // per-GT best guard (stale reads only under-admit; atomic decides)
            float cur = __uint_as_float(((const unsigned*)&s_best[m])[1]);
            if (iou > cur)
                atomicMax(&s_best[m],
                          ((unsigned long long)__float_as_uint(iou) << 32) | ip);
        }
        g_bt[b * PP + p] = bm | ((best >= 0.5f) ? 256 : 0);
    }
    __syncthreads();
    if (tid < MM && s_best[tid])
        atomicMax(&g_bp[b * MM + tid], s_best[tid]);
}

// ---------------------------------------------------------------------------
// Loss: contiguous priors, staged conf, reads g_bt; per-batch fixup + finalize.
__global__ void __launch_bounds__(TPB) k_loss(const float4* __restrict__ loc,
                                              const float*  __restrict__ conf,
                                              const float4* __restrict__ dbox,
                                              const float4* __restrict__ gt,
                                              const int*    __restrict__ glab,
                                              float* __restrict__ out)
{
    __shared__ float4 s_conf4[RPB * CC / 4];   // 43008 B, 16B-aligned cp.async dst
    __shared__ float4 s_g[MM];
    __shared__ int    s_lab[MM];
    __shared__ int    s_bp[MM];
    __shared__ float  s_red[16];
    __shared__ int    s_redi[8];
    __shared__ int    s_last;

    const float* s_conf = (const float*)s_conf4;

    int tid = threadIdx.x;
    int b = blockIdx.y;
    int p0 = blockIdx.x * RPB;
    int rows = min(RPB, PP - p0);              // 512 or 500; rows*CC % 4 == 0

    {
        const char* gsrc = (const char*)(conf + ((size_t)b * PP + (size_t)p0) * CC);
        unsigned sdst = (unsigned)__cvta_generic_to_shared(s_conf4);
        int n16 = rows * CC / 4;
        for (int i = tid; i < n16; i += TPB) {
            asm volatile("cp.async.ca.shared.global [%0], [%1], 16;\n"
                         :: "r"(sdst + i * 16), "l"(gsrc + (size_t)i * 16));
        }
        asm volatile("cp.async.commit_group;\n");
    }

    if (tid < MM) {
        s_g[tid]   = gt[b * MM + tid];
        s_lab[tid] = glab[b * MM + tid];
    }

    int p1 = p0 + tid;
    int p2 = p1 + TPB;
    bool v2 = (p2 < PP);
    int v1 = g_bt[b * PP + p1];
    int vv2 = v2 ? g_bt[b * PP + p2] : 0;

    asm volatile("cp.async.wait_group 0;\n" ::: "memory");
    __syncthreads();

    float fl = 0.0f, ll = 0.0f;
    int pos = 0;
    {
        int lab = (v1 & 256) ? s_lab[v1 & 255] : 0;
        fl += focal_term(&s_conf[tid * CC], lab);
        if (lab > 0) {
            pos++;
            ll += loc_term(dbox[p1], s_g[v1 & 255], loc[(size_t)b * PP + p1]);
        }
    }
    if (v2) {
        int lab = (vv2 & 256) ? s_lab[vv2 & 255] : 0;
        fl += focal_term(&s_conf[(tid + TPB) * CC], lab);
        if (lab > 0) {
            pos++;
            ll += loc_term(dbox[p2], s_g[vv2 & 255], loc[(size_t)b * PP + p2]);
        }
    }

    // ---- block reduction (8 warps) ----
    #pragma unroll
    for (int o = 16; o; o >>= 1) {
        fl  += __shfl_down_sync(0xFFFFFFFFu, fl, o);
        ll  += __shfl_down_sync(0xFFFFFFFFu, ll, o);
        pos += __shfl_down_sync(0xFFFFFFFFu, pos, o);
    }
    int wid = tid >> 5, lid = tid & 31;
    if (lid == 0) { s_red[wid] = fl; s_red[8 + wid] = ll; s_redi[wid] = pos; }
    __syncthreads();
    if (wid == 0) {
        float f  = (lid < 8) ? s_red[lid]     : 0.0f;
        float l2 = (lid < 8) ? s_red[8 + lid] : 0.0f;
        int   pc = (lid < 8) ? s_redi[lid]    : 0;
        #pragma unroll
        for (int o = 4; o; o >>= 1) {
            f  += __shfl_down_sync(0xFFFFFFFFu, f, o);
            l2 += __shfl_down_sync(0xFFFFFFFFu, l2, o);
            pc += __shfl_down_sync(0xFFFFFFFFu, pc, o);
        }
        if (lid == 0) {
            atomicAdd(&g_conf_sum, (double)f);
            atomicAdd(&g_loc_sum, (double)l2);
            atomicAdd(&g_npos, pc);
        }
    }

    // ---- per-batch completion: last block of batch b does the fixup ----
    __threadfence();
    __syncthreads();
    if (tid == 0) {
        unsigned t = atomicAdd(&g_done_b[b], 1u);
        s_last = (t == (unsigned)(GXL - 1)) ? 1 : 0;
    }
    __syncthreads();
    if (!s_last) return;

    __threadfence();
    if (tid < MM) {
        unsigned long long pk = g_bp[b * MM + tid];
        g_bp[b * MM + tid] = 0ull;             // reset for next run
        s_bp[tid] = (int)(0xFFFFFFFFu - (unsigned)(pk & 0xFFFFFFFFull));
    }
    __syncthreads();

    float dc = 0.0f, dl = 0.0f;
    int dp = 0;
    if (tid < MM) {
        int p = s_bp[tid];
        bool win = (p >= 0 && p < PP);
        for (int m2 = tid + 1; m2 < MM; m2++)  // duplicate p: largest m wins
            if (s_bp[m2] == p) win = false;
        if (win) {
            int v = g_bt[b * PP + p];
            int lab0 = (v & 256) ? s_lab[v & 255] : 0;
            const float* row = conf + ((size_t)b * PP + p) * CC;
            float fl0 = focal_term(row, lab0);         // cancels provisional
            float fl1 = focal_term(row, s_lab[tid]);   // forced label
            dc = fl1 - fl0;
            float4 dd = dbox[p];
            float4 l  = loc[(size_t)b * PP + p];
            float ll1 = loc_term(dd, s_g[tid], l);
            float ll0 = (lab0 > 0) ? loc_term(dd, s_g[v & 255], l) : 0.0f;
            dl = ll1 - ll0;
            dp = 1 - ((lab0 > 0) ? 1 : 0);
        }
    }
    #pragma unroll
    for (int o = 16; o; o >>= 1) {
        dc += __shfl_down_sync(0xFFFFFFFFu, dc, o);
        dl += __shfl_down_sync(0xFFFFFFFFu, dl, o);
        dp += __shfl_down_sync(0xFFFFFFFFu, dp, o);
    }
    if (lid == 0) { s_red[wid] = dc; s_red[8 + wid] = dl; s_redi[wid] = dp; }
    __syncthreads();
    if (tid == 0) {
        float f = s_red[0] + s_red[1];
        float l = s_red[8] + s_red[9];
        int  pc = s_redi[0] + s_redi[1];
        if (f != 0.0f) atomicAdd(&g_conf_sum, (double)f);
        if (l != 0.0f) atomicAdd(&g_loc_sum, (double)l);
        if (pc != 0)   atomicAdd(&g_npos, pc);
        g_done_b[b] = 0u;                      // reset for next run
        __threadfence();
        unsigned t = atomicAdd(&g_done, 1u);
        if (t == (unsigned)(BB - 1)) {         // globally last: finalize
            __threadfence();
            double ls = atomicAdd(&g_loc_sum, 0.0);
            double cs = atomicAdd(&g_conf_sum, 0.0);
            int np = atomicAdd(&g_npos, 0);
            double denom = (double)(np > 0 ? np : 1);
            float res = (float)(ls / denom) + (float)(cs / denom);
            out[0] = (np == 0) ? 0.0f : res;
            g_loc_sum = 0.0; g_conf_sum = 0.0; g_npos = 0; g_done = 0u;
        }
    }
}

// ---------------------------------------------------------------------------
extern "C" void kernel_launch(void* const* d_in, const int* in_sizes, int n_in,
                              void* d_out, int out_size) {
    const float4* loc  = (const float4*)d_in[0];  // [B,P,4]  f32
    const float*  conf = (const float*)d_in[1];   // [B,P,21] f32
    const float4* dbox = (const float4*)d_in[2];  // [P,4]    f32
    const float4* gt   = (const float4*)d_in[3];  // [B,50,4] f32
    const int*    glab = (const int*)d_in[4];     // [B,50]   i32
    float* out = (float*)d_out;

    k_prep0<<<1, 64>>>();
    k_bucket<<<(PP + 255) / 256, 256>>>(dbox);
    k_prep2<<<1, 32>>>();
    k_scatter<<<(PP + 255) / 256, 256>>>();
    dim3 gmm(NC, BB);
    k_match<<<gmm, TPB>>>(dbox, gt);
    dim3 gl(GXL, BB);
    k_loss<<<gl, TPB>>>(loc, conf, dbox, gt, glab, out);
}